// round 9
// baseline (speedup 1.0000x reference)
#include <cuda_runtime.h>

#define B_  64
#define T_  2048
#define H_  128
#define N3  384
#define BT  (B_ * T_)
#define LAG     128                  // inter-layer lag (multiple of 64)
#define NCHUNK  32
#define WAVES   (T_ + 2 * LAG)       // 2304
#define SCAN_CTAS 64
#define GEMM_CTAS 84
#define GRID      (SCAN_CTAS + GEMM_CTAS)   // 148, all resident

typedef unsigned long long ull;

// Scratch (allocation-free rule): 3 gx buffers (layers concurrently alive),
// 3 activation buffers (layer outputs), flags.
__device__ float g_gx0[(size_t)BT * N3];
__device__ float g_gx1[(size_t)BT * N3];
__device__ float g_gx2[(size_t)BT * N3];
__device__ float g_bufA[(size_t)BT * H_];
__device__ float g_bufB[(size_t)BT * H_];
__device__ float g_bufC[(size_t)BT * H_];
__device__ int g_cnt[3][B_][NCHUNK];   // gx chunk counters (target 3 n-tiles)
__device__ int g_rdy[3][B_][NCHUNK];   // scan chunk-done flags

// ---------------- packed f32x2 helpers (register-only asm: safe) -----------
__device__ __forceinline__ ull pk2(float lo, float hi) {
    ull r; asm("mov.b64 %0,{%1,%2};" : "=l"(r) : "f"(lo), "f"(hi)); return r;
}
__device__ __forceinline__ ull ffma2(ull a, ull b, ull c) {
    ull d; asm("fma.rn.f32x2 %0,%1,%2,%3;" : "=l"(d) : "l"(a), "l"(b), "l"(c)); return d;
}
__device__ __forceinline__ ull fadd2(ull a, ull b) {
    ull d; asm("add.rn.f32x2 %0,%1,%2;" : "=l"(d) : "l"(a), "l"(b)); return d;
}
__device__ __forceinline__ void unpk2(ull v, float& lo, float& hi) {
    asm("mov.b64 {%0,%1},%2;" : "=f"(lo), "=f"(hi) : "l"(v));
}
__device__ __forceinline__ unsigned smem_u32(const void* p) {
    unsigned a;
    asm("{.reg .u64 u; cvta.to.shared.u64 u,%1; cvt.u32.u64 %0,u;}" : "=r"(a) : "l"(p));
    return a;
}
// Volatile explicit-shared load: fast LDS.128 path, barrier-safe.
__device__ __forceinline__ void lds_v2u64(unsigned addr, ull& a, ull& b) {
    asm volatile("ld.shared.v2.u64 {%0,%1},[%2];" : "=l"(a), "=l"(b) : "r"(addr));
}
// Coherent L2 loads for intra-kernel-produced data (.cg skips L1 -> no staleness).
__device__ __forceinline__ float ldg_cg(const float* p) {
    float v; asm volatile("ld.global.cg.f32 %0,[%1];" : "=f"(v) : "l"(p)); return v;
}
__device__ __forceinline__ float4 ldg_cg4(const float* p) {
    float4 v;
    asm volatile("ld.global.cg.v4.f32 {%0,%1,%2,%3},[%4];"
                 : "=f"(v.x), "=f"(v.y), "=f"(v.z), "=f"(v.w) : "l"(p));
    return v;
}
// Acquire/release flag ops
__device__ __forceinline__ int ld_acq(const int* p) {
    int v; asm volatile("ld.acquire.gpu.global.b32 %0,[%1];" : "=r"(v) : "l"(p)); return v;
}
__device__ __forceinline__ void st_rel(int* p, int v) {
    asm volatile("st.release.gpu.global.b32 [%0],%1;" :: "l"(p), "r"(v) : "memory");
}
__device__ __forceinline__ void red_rel_add1(int* p) {
    asm volatile("red.release.gpu.global.add.s32 [%0],%1;" :: "l"(p), "r"(1) : "memory");
}

#define NLOG2E  (-1.442695040888963f)
#define N2LOG2E (-2.885390081777927f)

__device__ __forceinline__ float fsigmoid(float x) {
    float e = exp2f(fminf(x * NLOG2E, 126.f));
    return __fdividef(1.f, 1.f + e);
}

// 384-col recurrence dot for this thread's weight column against one h vector.
__device__ __forceinline__ float dot_h(unsigned haddr, const ull* __restrict__ w2) {
    ull a0 = 0ULL, a1 = 0ULL, a2 = 0ULL, a3 = 0ULL;
    #pragma unroll
    for (int q = 0; q < 8; q++) {
        ull hA0, hA1, hA2, hA3, hB0, hB1, hB2, hB3;
        const unsigned addr = haddr + q * 64;
        lds_v2u64(addr,      hA0, hA1);
        lds_v2u64(addr + 16, hA2, hA3);
        lds_v2u64(addr + 32, hB0, hB1);
        lds_v2u64(addr + 48, hB2, hB3);
        a0 = ffma2(hA0, w2[8 * q + 0], a0);
        a1 = ffma2(hA1, w2[8 * q + 1], a1);
        a2 = ffma2(hA2, w2[8 * q + 2], a2);
        a3 = ffma2(hA3, w2[8 * q + 3], a3);
        a0 = ffma2(hB0, w2[8 * q + 4], a0);
        a1 = ffma2(hB1, w2[8 * q + 5], a1);
        a2 = ffma2(hB2, w2[8 * q + 6], a2);
        a3 = ffma2(hB3, w2[8 * q + 7], a3);
    }
    a0 = fadd2(fadd2(a0, a1), fadd2(a2, a3));
    float lo, hi;
    unpk2(a0, lo, hi);
    return lo + hi;
}

// ---------------------------------------------------------------------------
// GEMM tile: C[m0:m0+64, n0:n0+128] = A[m0:,0:128] @ Bm[:, n0:] + bias
// All 384 threads enter (uniform barriers); tid<256 do the work.
// ---------------------------------------------------------------------------
__device__ void gemm_tile(
    const float* A, const float* __restrict__ Bm,
    const float* __restrict__ bias, float* __restrict__ C,
    int N, int m0, int n0, int applySigmoid,
    float (*sA)[33], float (*sB)[128])
{
    const int tid = threadIdx.x;
    const bool act = tid < 256;
    const int tx = tid & 15;
    const int ty = (tid >> 4) & 15;
    const int arow = (tid >> 3) & 31;
    const int akq  = tid & 7;
    const int brow = (tid >> 5) & 7;
    const int bcol = tid & 31;
    const unsigned sb_base = smem_u32(&sB[0][0]) + tx * 32;

    ull acc2[4][4];
    #pragma unroll
    for (int i = 0; i < 4; i++)
        #pragma unroll
        for (int j = 0; j < 4; j++) acc2[i][j] = 0ULL;

    for (int k0 = 0; k0 < 128; k0 += 32) {
        float4 a0, a1, b0, b1, b2, b3;
        if (act) {
            a0 = ldg_cg4(A + (size_t)(m0 + arow     ) * H_ + k0 + akq * 4);
            a1 = ldg_cg4(A + (size_t)(m0 + arow + 32) * H_ + k0 + akq * 4);
            b0 = *(const float4*)(Bm + (size_t)(k0 + brow     ) * N + n0 + bcol * 4);
            b1 = *(const float4*)(Bm + (size_t)(k0 + brow +  8) * N + n0 + bcol * 4);
            b2 = *(const float4*)(Bm + (size_t)(k0 + brow + 16) * N + n0 + bcol * 4);
            b3 = *(const float4*)(Bm + (size_t)(k0 + brow + 24) * N + n0 + bcol * 4);
        }
        __syncthreads();
        if (act) {
            sA[arow     ][akq * 4 + 0] = a0.x;  sA[arow     ][akq * 4 + 1] = a0.y;
            sA[arow     ][akq * 4 + 2] = a0.z;  sA[arow     ][akq * 4 + 3] = a0.w;
            sA[arow + 32][akq * 4 + 0] = a1.x;  sA[arow + 32][akq * 4 + 1] = a1.y;
            sA[arow + 32][akq * 4 + 2] = a1.z;  sA[arow + 32][akq * 4 + 3] = a1.w;
            *(float4*)&sB[brow     ][bcol * 4] = b0;
            *(float4*)&sB[brow +  8][bcol * 4] = b1;
            *(float4*)&sB[brow + 16][bcol * 4] = b2;
            *(float4*)&sB[brow + 24][bcol * 4] = b3;
        }
        __syncthreads();
        if (act) {
            #pragma unroll
            for (int k = 0; k < 32; k++) {
                ull pa[4];
                #pragma unroll
                for (int i = 0; i < 4; i++) {
                    float a = sA[ty * 4 + i][k];
                    pa[i] = pk2(a, a);
                }
                ull b01, b23, b45, b67;
                lds_v2u64(sb_base + k * 512,      b01, b23);
                lds_v2u64(sb_base + k * 512 + 16, b45, b67);
                #pragma unroll
                for (int i = 0; i < 4; i++) {
                    acc2[i][0] = ffma2(pa[i], b01, acc2[i][0]);
                    acc2[i][1] = ffma2(pa[i], b23, acc2[i][1]);
                    acc2[i][2] = ffma2(pa[i], b45, acc2[i][2]);
                    acc2[i][3] = ffma2(pa[i], b67, acc2[i][3]);
                }
            }
        }
    }

    if (act) {
        float bs[8];
        #pragma unroll
        for (int j = 0; j < 8; j++) bs[j] = bias[n0 + tx * 8 + j];
        #pragma unroll
        for (int i = 0; i < 4; i++) {
            const int row = m0 + ty * 4 + i;
            float v[8];
            #pragma unroll
            for (int j = 0; j < 4; j++) unpk2(acc2[i][j], v[2 * j], v[2 * j + 1]);
            #pragma unroll
            for (int j = 0; j < 8; j++) {
                float x = v[j] + bs[j];
                v[j] = applySigmoid ? fsigmoid(x) : x;
            }
            float4 o0 = {v[0], v[1], v[2], v[3]};
            float4 o1 = {v[4], v[5], v[6], v[7]};
            *(float4*)(C + (size_t)row * N + n0 + tx * 8    ) = o0;
            *(float4*)(C + (size_t)row * N + n0 + tx * 8 + 4) = o1;
        }
    }
}

__device__ __forceinline__ void wait_flag(const int* p, int target) {
    if (threadIdx.x == 0) {
        while (ld_acq(p) < target) __nanosleep(128);
    }
    __syncthreads();
}

__global__ void init_flags() {
    const int n = 3 * B_ * NCHUNK;
    int* a = &g_cnt[0][0][0];
    int* b = &g_rdy[0][0][0];
    for (int i = threadIdx.x; i < n; i += blockDim.x) { a[i] = 0; b[i] = 0; }
}

// ---------------------------------------------------------------------------
// Mega-kernel: 64 wavefront-scan CTAs + 84 GEMM workers, all resident (1/SM).
// Scan CTA runs all 3 layers concurrently (wavefront, layer l lags l*LAG),
// sharing the weight registers across layers (cells share rec_kernel).
// ---------------------------------------------------------------------------
__global__ void __launch_bounds__(384, 1) mega(
    const float* __restrict__ X,
    const float* __restrict__ kern,
    const float* __restrict__ rec,
    const float* __restrict__ b_in,
    const float* __restrict__ b_rec,
    const float* __restrict__ W_out,
    const float* __restrict__ b_out,
    float*       __restrict__ out)
{
    __shared__ __align__(16) float h0[H_];
    __shared__ __align__(16) float h1[H_];
    __shared__ __align__(16) float h2[H_];
    __shared__ float szs[3][H_];
    __shared__ float srs[3][H_];
    __shared__ float sA[64][33];
    __shared__ __align__(16) float sB[32][128];

    const int cta = blockIdx.x;
    const int t   = threadIdx.x;

    if (cta < SCAN_CTAS) {
        // ============== wavefront scan: batch b, 3 layers concurrent =======
        const int b    = cta;
        const int role = t >> 7;      // 0=z, 1=r, 2=h
        const int i    = t & 127;

        ull w2[64];
        #pragma unroll
        for (int j = 0; j < 64; j++)
            w2[j] = pk2(rec[(2 * j) * N3 + t], rec[(2 * j + 1) * N3 + t]);
        const float brec = b_rec[t];

        if (t < H_) { h0[t] = 0.f; h1[t] = 0.f; h2[t] = 0.f; }
        __syncthreads();

        const unsigned ha0 = smem_u32(h0);
        const unsigned ha1 = smem_u32(h1);
        const unsigned ha2 = smem_u32(h2);
        const float* gb0 = g_gx0 + (size_t)b * T_ * N3 + t;
        const float* gb1 = g_gx1 + (size_t)b * T_ * N3 + t;
        const float* gb2 = g_gx2 + (size_t)b * T_ * N3 + t;
        float* y0 = g_bufA + (size_t)b * T_ * H_ + i;
        float* y1 = g_bufB + (size_t)b * T_ * H_ + i;
        float* y2 = g_bufC + (size_t)b * T_ * H_ + i;

        for (int v = 0; v < WAVES; ++v) {
            const int s0 = v, s1 = v - LAG, s2 = v - 2 * LAG;
            const bool act0 = s0 < T_;
            const bool act1 = ((unsigned)s1) < (unsigned)T_;
            const bool act2 = ((unsigned)s2) < (unsigned)T_;

            if ((v & 63) == 0) {     // chunk boundary: all active layers aligned
                if (t == 0) {
                    if (act0) while (ld_acq(&g_cnt[0][b][s0 >> 6]) < 3) __nanosleep(64);
                    if (act1) while (ld_acq(&g_cnt[1][b][s1 >> 6]) < 3) __nanosleep(64);
                    if (act2) while (ld_acq(&g_cnt[2][b][s2 >> 6]) < 3) __nanosleep(64);
                }
                __syncthreads();
            }

            float gx0v = 0.f, gx1v = 0.f, gx2v = 0.f;
            if (act0) gx0v = ldg_cg(gb0 + (size_t)s0 * N3);
            if (act1) gx1v = ldg_cg(gb1 + (size_t)s1 * N3);
            if (act2) gx2v = ldg_cg(gb2 + (size_t)s2 * N3);

            float gh0 = 0.f, gh1 = 0.f, gh2 = 0.f;
            if (act0) gh0 = dot_h(ha0, w2) + brec;
            if (act1) gh1 = dot_h(ha1, w2) + brec;
            if (act2) gh2 = dot_h(ha2, w2) + brec;

            if (role == 0) {
                if (act0) szs[0][i] = fsigmoid(gx0v + gh0);
                if (act1) szs[1][i] = fsigmoid(gx1v + gh1);
                if (act2) szs[2][i] = fsigmoid(gx2v + gh2);
            } else if (role == 1) {
                if (act0) srs[0][i] = fsigmoid(gx0v + gh0);
                if (act1) srs[1][i] = fsigmoid(gx1v + gh1);
                if (act2) srs[2][i] = fsigmoid(gx2v + gh2);
            }
            __syncthreads();

            if (role == 2) {
                if (act0) {
                    float r = srs[0][i], z = szs[0][i];
                    float arg = fminf(fmaf(r, gh0 * N2LOG2E, gx0v * N2LOG2E), 126.f);
                    float c   = __fdividef(2.f, 1.f + exp2f(arg)) - 1.f;
                    float hn  = fmaf(z, h0[i] - c, c);
                    h0[i] = hn;
                    y0[(size_t)s0 * H_] = hn;
                }
                if (act1) {
                    float r = srs[1][i], z = szs[1][i];
                    float arg = fminf(fmaf(r, gh1 * N2LOG2E, gx1v * N2LOG2E), 126.f);
                    float c   = __fdividef(2.f, 1.f + exp2f(arg)) - 1.f;
                    float hn  = fmaf(z, h1[i] - c, c);
                    h1[i] = hn;
                    y1[(size_t)s1 * H_] = hn;
                }
                if (act2) {
                    float r = srs[2][i], z = szs[2][i];
                    float arg = fminf(fmaf(r, gh2 * N2LOG2E, gx2v * N2LOG2E), 126.f);
                    float c   = __fdividef(2.f, 1.f + exp2f(arg)) - 1.f;
                    float hn  = fmaf(z, h2[i] - c, c);
                    h2[i] = hn;
                    y2[(size_t)s2 * H_] = hn;
                }
            }
            __syncthreads();

            if ((v & 63) == 63) {    // publish finished chunks
                if (role == 2) __threadfence();
                __syncthreads();
                if (t == 0) {
                    if (act0) st_rel(&g_rdy[0][b][s0 >> 6], 1);
                    if (act1) st_rel(&g_rdy[1][b][s1 >> 6], 1);
                    if (act2) st_rel(&g_rdy[2][b][s2 >> 6], 1);
                }
            }
        }
    } else {
        // ================= GEMM worker =====================================
        const int wrk = cta - SCAN_CTAS;

        // Merged dependency-ordered gx list: block c holds gx0[c], gx1[c-2],
        // gx2[c-4] (192 tiles each). Stripe order is deadlock-free: every
        // item's dependency needs only strictly-earlier list items.
        const int NBLK = NCHUNK + 4;           // 36
        for (int idx = wrk; idx < NBLK * 576; idx += GEMM_CTAS) {
            const int blk = idx / 576;
            const int sub = idx % 576;
            const int l   = sub / 192;
            const int r   = sub % 192;
            const int c   = blk - 2 * l;
            if (c < 0 || c >= NCHUNK) continue;
            const int b = r / 3;
            const int n = r % 3;
            const float* Asrc = (l == 0) ? X : ((l == 1) ? g_bufA : g_bufB);
            float* dst = (l == 0) ? g_gx0 : ((l == 1) ? g_gx1 : g_gx2);
            if (l > 0) wait_flag(&g_rdy[l - 1][b][c], 1);
            gemm_tile(Asrc, kern, b_in, dst, N3,
                      b * T_ + c * 64, n * 128, 0, sA, sB);
            __threadfence();
            __syncthreads();
            if (t == 0) red_rel_add1(&g_cnt[l][b][c]);
        }
        // Output projection + sigmoid (consumes g_bufC), chunk-ordered.
        for (int idx = wrk; idx < NCHUNK * B_; idx += GEMM_CTAS) {
            const int c = idx / B_;
            const int b = idx % B_;
            wait_flag(&g_rdy[2][b][c], 1);
            gemm_tile(g_bufC, W_out, b_out, out, H_,
                      b * T_ + c * 64, 0, 1, sA, sB);
        }
    }
}

// ---------------------------------------------------------------------------
extern "C" void kernel_launch(void* const* d_in, const int* in_sizes, int n_in,
                              void* d_out, int out_size)
{
    const float* X     = (const float*)d_in[0];
    const float* kern  = (const float*)d_in[1];
    const float* rec   = (const float*)d_in[2];
    const float* b_in  = (const float*)d_in[3];
    const float* b_rec = (const float*)d_in[4];
    const float* W_out = (const float*)d_in[5];
    const float* b_out = (const float*)d_in[6];
    float* out = (float*)d_out;

    init_flags<<<1, 256>>>();
    mega<<<GRID, 384>>>(X, kern, rec, b_in, b_rec, W_out, b_out, out);
}